// round 5
// baseline (speedup 1.0000x reference)
#include <cuda_runtime.h>
#include <cstdint>

#define TM 32
#define THREADS 256

using ull = unsigned long long;

// ---- f32x2 packed math (Blackwell PTX-only path) ----
__device__ __forceinline__ ull pack2(float x) {
    ull r; unsigned u = __float_as_uint(x);
    asm("mov.b64 %0, {%1, %2};" : "=l"(r) : "r"(u), "r"(u));
    return r;
}
__device__ __forceinline__ ull fma2(ull a, ull b, ull c) {
    ull d;
    asm("fma.rn.f32x2 %0, %1, %2, %3;" : "=l"(d) : "l"(a), "l"(b), "l"(c));
    return d;
}
__device__ __forceinline__ void unpack2(ull v, float& lo, float& hi) {
    unsigned ulo, uhi;
    asm("mov.b64 {%0, %1}, %2;" : "=r"(ulo), "=r"(uhi) : "l"(v));
    lo = __uint_as_float(ulo); hi = __uint_as_float(uhi);
}

// ---- cp.async helpers ----
__device__ __forceinline__ void cp16(uint32_t dst, const void* src) {
    asm volatile("cp.async.cg.shared.global [%0], [%1], 16;" :: "r"(dst), "l"(src));
}
__device__ __forceinline__ void cp_commit() {
    asm volatile("cp.async.commit_group;");
}
template <int N> __device__ __forceinline__ void cp_wait() {
    asm volatile("cp.async.wait_group %0;" :: "n"(N));
}

// Shared layout (floats):
//  [0,     32768)  h0  (32x1024)   -- aliased by h2 (32x256) in layer2/3
//  [32768, 49152)  h1  (32x512)    -- aliased by W3+b3 stage in layer3
//  [49152, 57344)  w   (2 buffers x 4096 floats)
//  [57344, 57408)  coords (32x2)
#define SMEM_FLOATS 57408
#define SMEM_BYTES  (SMEM_FLOATS * 4)

__global__ void __launch_bounds__(THREADS, 1) ffn_kernel(
    const float* __restrict__ coord,
    const float* __restrict__ W0, const float* __restrict__ b0,
    const float* __restrict__ W1, const float* __restrict__ b1,
    const float* __restrict__ W2, const float* __restrict__ b2,
    const float* __restrict__ W3, const float* __restrict__ b3,
    float* __restrict__ out)
{
    extern __shared__ float sm[];
    float* sh0 = sm;            // h0 / h2
    float* sh1 = sm + 32768;    // h1 / W3 stage
    float* sw  = sm + 49152;    // weight tiles
    float* shc = sm + 57344;    // coords

    const int tid  = threadIdx.x;
    const int row0 = blockIdx.x * TM;

    const uint32_t sw_addr = (uint32_t)__cvta_generic_to_shared(sw);

    // ---------------- load coords ----------------
    if (tid < 64) shc[tid] = coord[row0 * 2 + tid];

    // Prefetch first two W1 tiles (8 rows x 512 = 4096 floats = 16KB each)
    {
        const float4* src = (const float4*)(W1);               // tile 0
        #pragma unroll
        for (int i = 0; i < 4; i++) {
            int e = tid + 256 * i;
            cp16(sw_addr + (uint32_t)(e * 16), src + e);
        }
        cp_commit();
        src = (const float4*)(W1 + 4096);                       // tile 1
        #pragma unroll
        for (int i = 0; i < 4; i++) {
            int e = tid + 256 * i;
            cp16(sw_addr + (uint32_t)(16384 + e * 16), src + e);
        }
        cp_commit();
    }

    __syncthreads();  // coords visible

    // ---------------- layer 0: h0 = relu(c @ W0 + b0) ----------------
    #pragma unroll
    for (int jt = 0; jt < 4; jt++) {
        int j = tid + 256 * jt;
        float w00 = W0[j], w01 = W0[1024 + j], bb = b0[j];
        #pragma unroll
        for (int m = 0; m < 32; m++) {
            float v = fmaf(shc[2 * m], w00, fmaf(shc[2 * m + 1], w01, bb));
            sh0[m * 1024 + j] = fmaxf(v, 0.0f);
        }
    }
    __syncthreads();

    // thread tiling for the GEMMs: 8 warps, warp = (m-group, n-half)
    const int wid = tid >> 5;
    const int tn  = tid & 31;
    const int m0  = (wid & 3) * 8;      // 8 rows per thread
    const int th  = wid >> 2;           // n half

    // ---------------- layer 1: h1 = relu(h0 @ W1 + b1)  [K=1024, N=512] ----
    {
        const int nb = th * 256 + 2 * tn;   // base column (pairs at +64*j)
        ull acc[8][4];
        #pragma unroll
        for (int r = 0; r < 8; r++)
            #pragma unroll
            for (int j = 0; j < 4; j++) acc[r][j] = 0ULL;

        for (int t = 0; t < 128; ++t) {
            if (t < 127) cp_wait<1>(); else cp_wait<0>();
            __syncthreads();

            const float* Wt = sw + ((t & 1) << 12);
            #pragma unroll
            for (int g = 0; g < 2; ++g) {
                float4 a4[8];
                #pragma unroll
                for (int r = 0; r < 8; ++r)
                    a4[r] = *(const float4*)&sh0[(m0 + r) * 1024 + t * 8 + g * 4];
                #pragma unroll
                for (int kk = 0; kk < 4; ++kk) {
                    const float* wrow = Wt + (g * 4 + kk) * 512 + nb;
                    ull w[4];
                    #pragma unroll
                    for (int j = 0; j < 4; ++j) w[j] = *(const ull*)(wrow + 64 * j);
                    #pragma unroll
                    for (int r = 0; r < 8; ++r) {
                        float av = (kk == 0) ? a4[r].x : (kk == 1) ? a4[r].y
                                 : (kk == 2) ? a4[r].z : a4[r].w;
                        ull a2 = pack2(av);
                        #pragma unroll
                        for (int j = 0; j < 4; ++j)
                            acc[r][j] = fma2(a2, w[j], acc[r][j]);
                    }
                }
            }
            __syncthreads();

            if (t + 2 < 128) {
                const float4* src = (const float4*)(W1 + (t + 2) * 4096);
                uint32_t base = sw_addr + (uint32_t)(((t + 2) & 1) * 16384);
                #pragma unroll
                for (int i = 0; i < 4; i++) {
                    int e = tid + 256 * i;
                    cp16(base + (uint32_t)(e * 16), src + e);
                }
                cp_commit();
            }
        }

        // epilogue: bias + relu -> sh1
        #pragma unroll
        for (int r = 0; r < 8; ++r) {
            #pragma unroll
            for (int j = 0; j < 4; ++j) {
                int col = nb + 64 * j;
                float lo, hi; unpack2(acc[r][j], lo, hi);
                float2 bb = *(const float2*)&b1[col];
                lo = fmaxf(lo + bb.x, 0.0f);
                hi = fmaxf(hi + bb.y, 0.0f);
                *(float2*)&sh1[(m0 + r) * 512 + col] = make_float2(lo, hi);
            }
        }
        __syncthreads();
    }

    // ---------------- layer 2: h2 = relu(h1 @ W2 + b2)  [K=512, N=256] ----
    {
        // prefetch first two W2 tiles (8 rows x 256 = 2048 floats = 8KB)
        {
            const float4* src = (const float4*)(W2);
            #pragma unroll
            for (int i = 0; i < 2; i++) {
                int e = tid + 256 * i;
                cp16(sw_addr + (uint32_t)(e * 16), src + e);
            }
            cp_commit();
            src = (const float4*)(W2 + 2048);
            #pragma unroll
            for (int i = 0; i < 2; i++) {
                int e = tid + 256 * i;
                cp16(sw_addr + (uint32_t)(16384 + e * 16), src + e);
            }
            cp_commit();
        }

        const int nb = th * 128 + 2 * tn;
        ull acc[8][2];
        #pragma unroll
        for (int r = 0; r < 8; r++) { acc[r][0] = 0ULL; acc[r][1] = 0ULL; }

        for (int t = 0; t < 64; ++t) {
            if (t < 63) cp_wait<1>(); else cp_wait<0>();
            __syncthreads();

            const float* Wt = sw + ((t & 1) << 12);
            #pragma unroll
            for (int g = 0; g < 2; ++g) {
                float4 a4[8];
                #pragma unroll
                for (int r = 0; r < 8; ++r)
                    a4[r] = *(const float4*)&sh1[(m0 + r) * 512 + t * 8 + g * 4];
                #pragma unroll
                for (int kk = 0; kk < 4; ++kk) {
                    const float* wrow = Wt + (g * 4 + kk) * 256 + nb;
                    ull w0v = *(const ull*)(wrow);
                    ull w1v = *(const ull*)(wrow + 64);
                    #pragma unroll
                    for (int r = 0; r < 8; ++r) {
                        float av = (kk == 0) ? a4[r].x : (kk == 1) ? a4[r].y
                                 : (kk == 2) ? a4[r].z : a4[r].w;
                        ull a2 = pack2(av);
                        acc[r][0] = fma2(a2, w0v, acc[r][0]);
                        acc[r][1] = fma2(a2, w1v, acc[r][1]);
                    }
                }
            }
            __syncthreads();

            if (t + 2 < 64) {
                const float4* src = (const float4*)(W2 + (t + 2) * 2048);
                uint32_t base = sw_addr + (uint32_t)(((t + 2) & 1) * 16384);
                #pragma unroll
                for (int i = 0; i < 2; i++) {
                    int e = tid + 256 * i;
                    cp16(base + (uint32_t)(e * 16), src + e);
                }
                cp_commit();
            }
        }

        // epilogue: bias + relu -> h2 (aliases sh0)
        #pragma unroll
        for (int r = 0; r < 8; ++r) {
            #pragma unroll
            for (int j = 0; j < 2; ++j) {
                int col = nb + 64 * j;
                float lo, hi; unpack2(acc[r][j], lo, hi);
                float2 bb = *(const float2*)&b2[col];
                lo = fmaxf(lo + bb.x, 0.0f);
                hi = fmaxf(hi + bb.y, 0.0f);
                *(float2*)&sh0[(m0 + r) * 256 + col] = make_float2(lo, hi);
            }
        }
        __syncthreads();
    }

    // ---------------- layer 3: out = h2 @ W3 + b3  [K=256, N=3] ----------
    // stage W3 (256x3 = 768 floats) + b3 into sh1 (free now).
    // NOTE: grid-stride — 768 > THREADS (this was the R2 correctness bug).
    for (int i = tid; i < 768; i += THREADS) sh1[i] = W3[i];
    if (tid < 3) sh1[768 + tid] = b3[tid];
    __syncthreads();

    if (tid < 96) {
        int m = tid / 3;
        int c = tid - m * 3;
        float acc = sh1[768 + c];
        #pragma unroll 8
        for (int k4 = 0; k4 < 64; ++k4) {
            float4 h = *(const float4*)&sh0[m * 256 + 4 * k4];
            acc = fmaf(h.x, sh1[(4 * k4 + 0) * 3 + c], acc);
            acc = fmaf(h.y, sh1[(4 * k4 + 1) * 3 + c], acc);
            acc = fmaf(h.z, sh1[(4 * k4 + 2) * 3 + c], acc);
            acc = fmaf(h.w, sh1[(4 * k4 + 3) * 3 + c], acc);
        }
        out[(row0 + m) * 3 + c] = acc;
    }
}

extern "C" void kernel_launch(void* const* d_in, const int* in_sizes, int n_in,
                              void* d_out, int out_size) {
    const float* coord = (const float*)d_in[0];
    const float* W0 = (const float*)d_in[1];
    const float* b0 = (const float*)d_in[2];
    const float* W1 = (const float*)d_in[3];
    const float* b1 = (const float*)d_in[4];
    const float* W2 = (const float*)d_in[5];
    const float* b2 = (const float*)d_in[6];
    const float* W3 = (const float*)d_in[7];
    const float* b3 = (const float*)d_in[8];
    float* out = (float*)d_out;

    int N = in_sizes[0] / 2;  // 262144
    int grid = N / TM;        // 8192

    cudaFuncSetAttribute(ffn_kernel,
                         cudaFuncAttributeMaxDynamicSharedMemorySize, SMEM_BYTES);
    ffn_kernel<<<grid, THREADS, SMEM_BYTES>>>(coord, W0, b0, W1, b1, W2, b2,
                                              W3, b3, out);
}

// round 8
// speedup vs baseline: 10.1177x; 10.1177x over previous
#include <cuda_runtime.h>
#include <cstdint>

#define THREADS 256

// Arch-specific (sm_103a/sm_100a) feature gate: tcgen05 only exists on 'a' targets.
#if defined(__CUDA_ARCH_FEAT_SM103_ALL) || defined(__CUDA_ARCH_FEAT_SM100_ALL) || defined(__CUDA_ARCH_SPECIFIC__)
#define HAS_TCGEN05 1
#else
#define HAS_TCGEN05 0
#endif

// ---------------- device scratch (static: no allocation) ----------------
__device__ float g_W1T[512 * 1024];        // W1 transposed, tf32-rounded (K-major B)
__device__ float g_W2T[256 * 512];         // W2 transposed, tf32-rounded
__device__ float g_h1[262144ULL * 512];    // layer-1 activations (512 MB)

// ---------------- helpers (legal on all targets) ----------------
__device__ __forceinline__ uint32_t s2u(const void* p) {
    uint32_t a;
    asm("{ .reg .u64 t; cvta.to.shared.u64 t, %1; cvt.u32.u64 %0, t; }" : "=r"(a) : "l"(p));
    return a;
}
__device__ __forceinline__ float to_tf32(float x) {
    float r; asm("cvt.rna.tf32.f32 %0, %1;" : "=f"(r) : "f"(x)); return r;
}
__device__ __forceinline__ void cp16(uint32_t dst, const void* src) {
    asm volatile("cp.async.cg.shared.global [%0], [%1], 16;" :: "r"(dst), "l"(src));
}
__device__ __forceinline__ void cp_commit() { asm volatile("cp.async.commit_group;"); }
template <int N> __device__ __forceinline__ void cp_wait() {
    asm volatile("cp.async.wait_group %0;" :: "n"(N));
}
#define SW(o) ((o) ^ (((o) >> 3) & 0x70))

#if HAS_TCGEN05
__device__ __forceinline__ uint32_t elect1() {
    uint32_t p;
    asm volatile("{ .reg .pred p; elect.sync _|p, 0xFFFFFFFF; selp.b32 %0, 1, 0, p; }" : "=r"(p));
    return p;
}

#define MBARRIER_INIT(addr, cnt) \
    asm volatile("mbarrier.init.shared.b64 [%0], %1;" :: "r"((uint32_t)(addr)), "r"((uint32_t)(cnt)) : "memory")

#define MBAR_WAIT(addr, parity) do {                                              \
    uint32_t _mb = (uint32_t)(addr); uint32_t _pa = (uint32_t)(parity);           \
    asm volatile("{\n\t.reg .pred P1;\n\t"                                        \
        "WAIT_LOOP_%=:\n\t"                                                       \
        "mbarrier.try_wait.parity.acquire.cta.shared::cta.b64 P1, [%0], %1, 0x989680;\n\t" \
        "@P1 bra.uni WAIT_DONE_%=;\n\t"                                           \
        "bra.uni WAIT_LOOP_%=;\n\t"                                               \
        "WAIT_DONE_%=:\n\t}"                                                      \
        :: "r"(_mb), "r"(_pa) : "memory");                                        \
} while (0)

#define LDTM32(r, addr) \
    asm volatile("tcgen05.ld.sync.aligned.32x32b.x32.b32 " \
        "{%0, %1, %2, %3, %4, %5, %6, %7, %8, %9, %10, %11, %12, %13, %14, %15, " \
        "%16, %17, %18, %19, %20, %21, %22, %23, %24, %25, %26, %27, %28, %29, %30, %31}, [%32];" \
        : "=r"((r)[0]), "=r"((r)[1]), "=r"((r)[2]), "=r"((r)[3]),   \
          "=r"((r)[4]), "=r"((r)[5]), "=r"((r)[6]), "=r"((r)[7]),   \
          "=r"((r)[8]), "=r"((r)[9]), "=r"((r)[10]), "=r"((r)[11]), \
          "=r"((r)[12]), "=r"((r)[13]), "=r"((r)[14]), "=r"((r)[15]),\
          "=r"((r)[16]), "=r"((r)[17]), "=r"((r)[18]), "=r"((r)[19]),\
          "=r"((r)[20]), "=r"((r)[21]), "=r"((r)[22]), "=r"((r)[23]),\
          "=r"((r)[24]), "=r"((r)[25]), "=r"((r)[26]), "=r"((r)[27]),\
          "=r"((r)[28]), "=r"((r)[29]), "=r"((r)[30]), "=r"((r)[31]) \
        : "r"(addr))

__device__ __forceinline__ uint64_t DESC(uint32_t addr) {
    // SW128 K-major: layout=2, version=1, SBO=64 (1024B / 8 rows), LBO=1 (16B)
    return (2ULL << 61) | (1ULL << 46) | (64ULL << 32) | (1ULL << 16)
         | (uint64_t)((addr >> 4) & 0x3FFF);
}

// tf32 SS MMA, cta_group::1: D[128x256] += A[128xK8] @ B[256xK8]^T
__device__ __forceinline__ void mma_tf32_ss(uint32_t d, uint64_t ad, uint64_t bd,
                                            uint32_t idesc, uint32_t en) {
    asm volatile("{\n\t.reg .pred p;\n\tsetp.ne.u32 p, %4, 0;\n\t"
        "tcgen05.mma.cta_group::1.kind::tf32 [%0], %1, %2, %3, {%5, %5, %5, %5}, p;\n\t}"
        :: "r"(d), "l"(ad), "l"(bd), "r"(idesc), "r"(en), "r"(0u) : "memory");
}

// idesc: dtype=F32(1)<<4, atype=TF32(2)<<7, btype=TF32(2)<<10, N/8<<17, M/16<<24
#define IDESC_TF32 ((1u << 4) | (2u << 7) | (2u << 10) | ((256u / 8) << 17) | ((128u / 16) << 24))
#endif  // HAS_TCGEN05

// ---------------- prep: transpose + tf32 rounding ----------------
__global__ void tr_kernel(const float* __restrict__ src, int R, int C, int which) {
    float* dst = which ? g_W2T : g_W1T;   // dst is [C][R]
    __shared__ float tile[32][33];
    int bx = blockIdx.x, by = blockIdx.y;
    int tx = threadIdx.x, ty = threadIdx.y;   // block (32, 8)
    #pragma unroll
    for (int i = 0; i < 4; i++)
        tile[ty + 8 * i][tx] = src[(size_t)(by * 32 + ty + 8 * i) * C + bx * 32 + tx];
    __syncthreads();
    #pragma unroll
    for (int i = 0; i < 4; i++)
        dst[(size_t)(bx * 32 + ty + 8 * i) * R + by * 32 + tx] = to_tf32(tile[tx][ty + 8 * i]);
}

// ---------------- K1: layers 0+1 fused -> h1 ----------------
// grid (1024, 2): 256 rows per CTA, 256-col N-half per CTA. K=1024, KC=32.
#define K1_SM_A  0                   // 3 x 32768  (A tiles 256x32 f32)
#define K1_SM_B  98304               // 3 x 32768  (B tiles 256x32 f32)
#define K1_SM_W0 196608              // 2048 f
#define K1_SM_B0 204800              // 1024 f
#define K1_SM_CO 208896              // 512 f
#define K1_SM_BI 210944              // 256 f
#define K1_SM_TP 211968
#define K1_SM_MB 211976
#define K1_SMEM  212096

__global__ void __launch_bounds__(THREADS, 1) k1_kernel(
    const float* __restrict__ coord, const float* __restrict__ W0,
    const float* __restrict__ b0, const float* __restrict__ W1,
    const float* __restrict__ b1)
{
#if HAS_TCGEN05
    extern __shared__ char sm[];
    const uint32_t smb = s2u(sm);
    const int tid  = threadIdx.x;
    const int row0 = blockIdx.x * 256;
    const int n0   = blockIdx.y * 256;

    if (tid < 32)
        asm volatile("tcgen05.alloc.cta_group::1.sync.aligned.shared::cta.b32 [%0], %1;"
                     :: "r"(smb + K1_SM_TP), "r"(512) : "memory");
    if (tid == 0) { MBARRIER_INIT(smb + K1_SM_MB, 1); MBARRIER_INIT(smb + K1_SM_MB + 8, 1); }

    float* sW0 = (float*)(sm + K1_SM_W0);
    float* sB0 = (float*)(sm + K1_SM_B0);
    float* sCO = (float*)(sm + K1_SM_CO);
    float* sBI = (float*)(sm + K1_SM_BI);
    for (int i = tid; i < 2048; i += 256) sW0[i] = W0[i];
    for (int i = tid; i < 1024; i += 256) sB0[i] = b0[i];
    ((float2*)sCO)[tid] = ((const float2*)coord)[row0 + tid];
    sBI[tid] = b1[n0 + tid];

    // prefetch B(0): one W1T row per thread, 32 floats = 8 x 16B
    {
        const float* src = g_W1T + (size_t)(n0 + tid) * 1024;
        uint32_t db = smb + K1_SM_B;
        #pragma unroll
        for (int g = 0; g < 8; g++) cp16(db + SW(tid * 128 + g * 16), src + g * 4);
        cp_commit();
    }
    __syncthreads();

    uint32_t tmem;
    asm volatile("ld.shared.b32 %0, [%1];" : "=r"(tmem) : "r"(smb + K1_SM_TP));
    const float c0 = sCO[2 * tid], c1 = sCO[2 * tid + 1];

    int ph0 = 0, ph1 = 0;
    for (int t = 0; t < 32; ++t) {
        if (t >= 2) {                                  // MMA(t-2) done -> slots free
            if (t & 1) { MBAR_WAIT(smb + K1_SM_MB + 8, ph1); ph1 ^= 1; }
            else       { MBAR_WAIT(smb + K1_SM_MB,     ph0); ph0 ^= 1; }
        }
        if (t + 1 < 32) {                              // prefetch B(t+1)
            const float* src = g_W1T + (size_t)(n0 + tid) * 1024 + (t + 1) * 32;
            uint32_t db = smb + K1_SM_B + ((t + 1) % 3) * 32768;
            #pragma unroll
            for (int g = 0; g < 8; g++) cp16(db + SW(tid * 128 + g * 16), src + g * 4);
            cp_commit();
        }
        {                                              // compute A(t) = h0 chunk (layer 0)
            char* ab = sm + K1_SM_A + (t % 3) * 32768;
            #pragma unroll
            for (int q = 0; q < 8; ++q) {
                int k = t * 32 + q * 4;
                float4 wa = *(const float4*)&sW0[k];
                float4 wb = *(const float4*)&sW0[1024 + k];
                float4 bb = *(const float4*)&sB0[k];
                float4 v;
                v.x = to_tf32(fmaxf(fmaf(c0, wa.x, fmaf(c1, wb.x, bb.x)), 0.f));
                v.y = to_tf32(fmaxf(fmaf(c0, wa.y, fmaf(c1, wb.y, bb.y)), 0.f));
                v.z = to_tf32(fmaxf(fmaf(c0, wa.z, fmaf(c1, wb.z, bb.z)), 0.f));
                v.w = to_tf32(fmaxf(fmaf(c0, wa.w, fmaf(c1, wb.w, bb.w)), 0.f));
                *(float4*)(ab + SW(tid * 128 + q * 16)) = v;
            }
        }
        if (t + 1 < 32) cp_wait<1>(); else cp_wait<0>();
        asm volatile("fence.proxy.async.shared::cta;" ::: "memory");
        __syncthreads();
        if (tid < 32 && elect1()) {
            uint64_t ad = DESC(smb + K1_SM_A + (t % 3) * 32768);
            uint64_t bd = DESC(smb + K1_SM_B + (t % 3) * 32768);
            #pragma unroll
            for (int s = 0; s < 4; ++s) {
                uint32_t en = (t > 0 || s > 0) ? 1u : 0u;
                mma_tf32_ss(tmem,       ad + 2 * s,        bd + 2 * s, IDESC_TF32, en);
                mma_tf32_ss(tmem + 256, ad + 1024 + 2 * s, bd + 2 * s, IDESC_TF32, en);
            }
            asm volatile("tcgen05.commit.cta_group::1.mbarrier::arrive::one.shared::cluster.b64 [%0];"
                         :: "r"(smb + K1_SM_MB + (t & 1) * 8) : "memory");
        }
    }
    MBAR_WAIT(smb + K1_SM_MB,     ph0);
    MBAR_WAIT(smb + K1_SM_MB + 8, ph1);
    asm volatile("tcgen05.fence::after_thread_sync;" ::: "memory");

    // epilogue: bias + relu + tf32 round -> h1
    const int w = tid >> 5, lane = tid & 31;
    const int sub = w >> 2;
    const int grow = row0 + sub * 128 + ((w & 3) << 5) + lane;
    float* h1row = g_h1 + (size_t)grow * 512 + n0;
    #pragma unroll
    for (int cc = 0; cc < 8; ++cc) {
        uint32_t r[32];
        LDTM32(r, tmem + sub * 256 + cc * 32);
        asm volatile("tcgen05.wait::ld.sync.aligned;" ::: "memory");
        #pragma unroll
        for (int q = 0; q < 8; ++q) {
            float4 bb = *(const float4*)&sBI[cc * 32 + q * 4];
            float4 v;
            v.x = to_tf32(fmaxf(__uint_as_float(r[q * 4 + 0]) + bb.x, 0.f));
            v.y = to_tf32(fmaxf(__uint_as_float(r[q * 4 + 1]) + bb.y, 0.f));
            v.z = to_tf32(fmaxf(__uint_as_float(r[q * 4 + 2]) + bb.z, 0.f));
            v.w = to_tf32(fmaxf(__uint_as_float(r[q * 4 + 3]) + bb.w, 0.f));
            *(float4*)&h1row[cc * 32 + q * 4] = v;
        }
    }
    __syncthreads();
    if (tid < 32) {
        asm volatile("tcgen05.relinquish_alloc_permit.cta_group::1.sync.aligned;");
        asm volatile("tcgen05.dealloc.cta_group::1.sync.aligned.b32 %0, %1;" :: "r"(tmem), "r"(512));
    }
#else
    // -------- fallback (non-103a compile pass): plain-FMA, same semantics --------
    extern __shared__ char sm[];
    float* h0g = (float*)sm;                       // 8 x 1024 floats
    const int tid  = threadIdx.x;
    const int row0 = blockIdx.x * 256;
    const int n0   = blockIdx.y * 256;
    const int rg   = tid >> 5, lane = tid & 31;
    const int cbase = n0 + lane * 8;

    for (int g = 0; g < 32; ++g) {                 // 8-row groups
        int rbase = row0 + g * 8;
        for (int i = tid; i < 8192; i += 256) {
            int r = i >> 10, k = i & 1023;
            float c0 = coord[(rbase + r) * 2], c1 = coord[(rbase + r) * 2 + 1];
            h0g[i] = fmaxf(fmaf(c0, W0[k], fmaf(c1, W0[1024 + k], b0[k])), 0.f);
        }
        __syncthreads();
        float acc[8];
        #pragma unroll
        for (int j = 0; j < 8; j++) acc[j] = b1[cbase + j];
        for (int k = 0; k < 1024; ++k) {
            float a = h0g[rg * 1024 + k];
            float4 w0_ = *(const float4*)&W1[(size_t)k * 512 + cbase];
            float4 w1_ = *(const float4*)&W1[(size_t)k * 512 + cbase + 4];
            acc[0] = fmaf(a, w0_.x, acc[0]); acc[1] = fmaf(a, w0_.y, acc[1]);
            acc[2] = fmaf(a, w0_.z, acc[2]); acc[3] = fmaf(a, w0_.w, acc[3]);
            acc[4] = fmaf(a, w1_.x, acc[4]); acc[5] = fmaf(a, w1_.y, acc[5]);
            acc[6] = fmaf(a, w1_.z, acc[6]); acc[7] = fmaf(a, w1_.w, acc[7]);
        }
        float* dst = g_h1 + (size_t)(rbase + rg) * 512 + cbase;
        #pragma unroll
        for (int j = 0; j < 8; j++) dst[j] = fmaxf(acc[j], 0.f);
        __syncthreads();
    }
#endif
}

// ---------------- K2: layers 2+3 fused -> out ----------------
// grid (1024): 256 rows per CTA, N=256 (full). K=512, KC=32, 16 chunks.
#define K2_SM_A   0                  // 3 x 32768
#define K2_SM_B   98304              // 3 x 32768
#define K2_SM_B2  196608             // 256 f
#define K2_SM_W3  197632             // 1024 f (padded 4/col)
#define K2_SM_B3  201728             // 4 f
#define K2_SM_TP  201744
#define K2_SM_MB  201752
#define K2_SMEM   201856

__global__ void __launch_bounds__(THREADS, 1) k2_kernel(
    const float* __restrict__ W2, const float* __restrict__ b2,
    const float* __restrict__ W3, const float* __restrict__ b3,
    float* __restrict__ out)
{
#if HAS_TCGEN05
    extern __shared__ char sm[];
    const uint32_t smb = s2u(sm);
    const int tid  = threadIdx.x;
    const int row0 = blockIdx.x * 256;

    if (tid < 32)
        asm volatile("tcgen05.alloc.cta_group::1.sync.aligned.shared::cta.b32 [%0], %1;"
                     :: "r"(smb + K2_SM_TP), "r"(512) : "memory");
    if (tid == 0) { MBARRIER_INIT(smb + K2_SM_MB, 1); MBARRIER_INIT(smb + K2_SM_MB + 8, 1); }

    float* sB2 = (float*)(sm + K2_SM_B2);
    float* sW3 = (float*)(sm + K2_SM_W3);
    float* sB3 = (float*)(sm + K2_SM_B3);
    sB2[tid] = b2[tid];
    for (int i = tid; i < 768; i += 256) sW3[(i / 3) * 4 + (i % 3)] = W3[i];
    if (tid < 3) sB3[tid] = b3[tid];

    // prefetch A(0), B(0) as one cp.async group
    {
        const float* sa = g_h1 + (size_t)(row0 + tid) * 512;
        const float* sb = g_W2T + (size_t)tid * 512;
        uint32_t da = smb + K2_SM_A, db = smb + K2_SM_B;
        #pragma unroll
        for (int g = 0; g < 8; g++) cp16(da + SW(tid * 128 + g * 16), sa + g * 4);
        #pragma unroll
        for (int g = 0; g < 8; g++) cp16(db + SW(tid * 128 + g * 16), sb + g * 4);
        cp_commit();
    }
    __syncthreads();

    uint32_t tmem;
    asm volatile("ld.shared.b32 %0, [%1];" : "=r"(tmem) : "r"(smb + K2_SM_TP));

    int ph0 = 0, ph1 = 0;
    for (int t = 0; t < 16; ++t) {
        if (t >= 2) {
            if (t & 1) { MBAR_WAIT(smb + K2_SM_MB + 8, ph1); ph1 ^= 1; }
            else       { MBAR_WAIT(smb + K2_SM_MB,     ph0); ph0 ^= 1; }
        }
        if (t + 1 < 16) {
            const float* sa = g_h1 + (size_t)(row0 + tid) * 512 + (t + 1) * 32;
            const float* sb = g_W2T + (size_t)tid * 512 + (t + 1) * 32;
            uint32_t da = smb + K2_SM_A + ((t + 1) % 3) * 32768;
            uint32_t db = smb + K2_SM_B + ((t + 1) % 3) * 32768;
            #pragma unroll
            for (int g = 0; g < 8; g++) cp16(da + SW(tid * 128 + g * 16), sa + g * 4);
            #pragma unroll
            for (int g = 0; g < 8; g++) cp16(db + SW(tid * 128 + g * 16), sb + g * 4);
            cp_commit();
        }
        if (t + 1 < 16) cp_wait<1>(); else cp_wait<0>();
        asm volatile("fence.proxy.async.shared::cta;" ::: "memory");
        __syncthreads();
        if (tid < 32 && elect1()) {
            uint64_t ad = DESC(smb + K2_SM_A + (t % 3) * 32768);
            uint64_t bd = DESC(smb + K2_SM_B + (t % 3) * 32768);
            #pragma unroll
            for (int s = 0; s < 4; ++s) {
                uint32_t en = (t > 0 || s > 0) ? 1u : 0u;
                mma_tf32_ss(tmem,       ad + 2 * s,        bd + 2 * s, IDESC_TF32, en);
                mma_tf32_ss(tmem + 256, ad + 1024 + 2 * s, bd + 2 * s, IDESC_TF32, en);
            }
            asm volatile("tcgen05.commit.cta_group::1.mbarrier::arrive::one.shared::cluster.b64 [%0];"
                         :: "r"(smb + K2_SM_MB + (t & 1) * 8) : "memory");
        }
    }
    MBAR_WAIT(smb + K2_SM_MB,     ph0);
    MBAR_WAIT(smb + K2_SM_MB + 8, ph1);
    asm volatile("tcgen05.fence::after_thread_sync;" ::: "memory");

    // epilogue: h2 = relu(D + b2); out = h2 @ W3 + b3 (h2 never hits global)
    const int w = tid >> 5, lane = tid & 31;
    const int sub = w >> 2;
    const int grow = row0 + sub * 128 + ((w & 3) << 5) + lane;
    float a0 = 0.f, a1 = 0.f, a2 = 0.f;
    #pragma unroll
    for (int cc = 0; cc < 8; ++cc) {
        uint32_t r[32];
        LDTM32(r, tmem + sub * 256 + cc * 32);
        asm volatile("tcgen05.wait::ld.sync.aligned;" ::: "memory");
        #pragma unroll
        for (int q = 0; q < 8; ++q) {
            float4 bb = *(const float4*)&sB2[cc * 32 + q * 4];
            #pragma unroll
            for (int m = 0; m < 4; ++m) {
                float bbm = (m == 0) ? bb.x : (m == 1) ? bb.y : (m == 2) ? bb.z : bb.w;
                float h = fmaxf(__uint_as_float(r[q * 4 + m]) + bbm, 0.f);
                float4 w3 = *(const float4*)&sW3[(cc * 32 + q * 4 + m) * 4];
                a0 = fmaf(h, w3.x, a0);
                a1 = fmaf(h, w3.y, a1);
                a2 = fmaf(h, w3.z, a2);
            }
        }
    }
    out[(size_t)grow * 3 + 0] = a0 + sB3[0];
    out[(size_t)grow * 3 + 1] = a1 + sB3[1];
    out[(size_t)grow * 3 + 2] = a2 + sB3[2];

    __syncthreads();
    if (tid < 32) {
        asm volatile("tcgen05.relinquish_alloc_permit.cta_group::1.sync.aligned;");
        asm volatile("tcgen05.dealloc.cta_group::1.sync.aligned.b32 %0, %1;" :: "r"(tmem), "r"(512));
    }
#else
    // -------- fallback (non-103a compile pass): plain-FMA, same semantics --------
    extern __shared__ char sm[];
    float* h1g = (float*)sm;                       // 8 x 512
    float* h2g = h1g + 4096;                       // 8 x 256
    const int tid  = threadIdx.x;
    const int row0 = blockIdx.x * 256;
    const int rg   = tid >> 5, lane = tid & 31;
    const int cbase = lane * 8;

    for (int g = 0; g < 32; ++g) {
        int rbase = row0 + g * 8;
        for (int i = tid; i < 4096; i += 256)
            h1g[i] = g_h1[(size_t)(rbase + (i >> 9)) * 512 + (i & 511)];
        __syncthreads();
        float acc[8];
        #pragma unroll
        for (int j = 0; j < 8; j++) acc[j] = b2[cbase + j];
        for (int k = 0; k < 512; ++k) {
            float a = h1g[rg * 512 + k];
            float4 w0_ = *(const float4*)&W2[(size_t)k * 256 + cbase];
            float4 w1_ = *(const float4*)&W2[(size_t)k * 256 + cbase + 4];
            acc[0] = fmaf(a, w0_.x, acc[0]); acc[1] = fmaf(a, w0_.y, acc[1]);
            acc[2] = fmaf(a, w0_.z, acc[2]); acc[3] = fmaf(a, w0_.w, acc[3]);
            acc[4] = fmaf(a, w1_.x, acc[4]); acc[5] = fmaf(a, w1_.y, acc[5]);
            acc[6] = fmaf(a, w1_.z, acc[6]); acc[7] = fmaf(a, w1_.w, acc[7]);
        }
        #pragma unroll
        for (int j = 0; j < 8; j++) h2g[rg * 256 + cbase + j] = fmaxf(acc[j], 0.f);
        __syncthreads();
        if (tid < 24) {
            int m = tid / 3, c = tid - m * 3;
            float s = b3[c];
            for (int k = 0; k < 256; ++k) s = fmaf(h2g[m * 256 + k], W3[k * 3 + c], s);
            out[(size_t)(rbase + m) * 3 + c] = s;
        }
        __syncthreads();
    }
#endif
}

// ---------------- launch ----------------
extern "C" void kernel_launch(void* const* d_in, const int* in_sizes, int n_in,
                              void* d_out, int out_size) {
    const float* coord = (const float*)d_in[0];
    const float* W0 = (const float*)d_in[1];
    const float* b0 = (const float*)d_in[2];
    const float* W1 = (const float*)d_in[3];
    const float* b1 = (const float*)d_in[4];
    const float* W2 = (const float*)d_in[5];
    const float* b2 = (const float*)d_in[6];
    const float* W3 = (const float*)d_in[7];
    const float* b3 = (const float*)d_in[8];
    float* out = (float*)d_out;

    cudaFuncSetAttribute(k1_kernel, cudaFuncAttributeMaxDynamicSharedMemorySize, K1_SMEM);
    cudaFuncSetAttribute(k2_kernel, cudaFuncAttributeMaxDynamicSharedMemorySize, K2_SMEM);

    // prep: W1 [1024x512] -> W1T [512x1024]; W2 [512x256] -> W2T [256x512]
    tr_kernel<<<dim3(512 / 32, 1024 / 32), dim3(32, 8)>>>(W1, 1024, 512, 0);
    tr_kernel<<<dim3(256 / 32,  512 / 32), dim3(32, 8)>>>(W2,  512, 256, 1);

    // layers 0+1 -> h1
    k1_kernel<<<dim3(1024, 2), THREADS, K1_SMEM>>>(coord, W0, b0, W1, b1);
    // layers 2+3 -> out
    k2_kernel<<<dim3(1024, 1), THREADS, K2_SMEM>>>(W2, b2, W3, b3, out);
}

// round 9
// speedup vs baseline: 17.0743x; 1.6876x over previous
#include <cuda_runtime.h>
#include <cstdint>

#define THREADS 256

// Arch-specific (sm_103a/sm_100a) feature gate: tcgen05 only exists on 'a' targets.
#if defined(__CUDA_ARCH_FEAT_SM103_ALL) || defined(__CUDA_ARCH_FEAT_SM100_ALL) || defined(__CUDA_ARCH_SPECIFIC__)
#define HAS_TCGEN05 1
#else
#define HAS_TCGEN05 0
#endif

// ---------------- device scratch (static: no allocation) ----------------
__device__ float g_W1T[512 * 1024];        // W1 transposed, tf32-rounded (K-major B)
__device__ float g_W2T[256 * 512];         // W2 transposed, tf32-rounded
__device__ float g_h1[262144ULL * 512];    // layer-1 activations (512 MB)

// ---------------- helpers (legal on all targets) ----------------
__device__ __forceinline__ uint32_t s2u(const void* p) {
    uint32_t a;
    asm("{ .reg .u64 t; cvta.to.shared.u64 t, %1; cvt.u32.u64 %0, t; }" : "=r"(a) : "l"(p));
    return a;
}
__device__ __forceinline__ float to_tf32(float x) {
    float r; asm("cvt.rna.tf32.f32 %0, %1;" : "=f"(r) : "f"(x)); return r;
}
__device__ __forceinline__ void cp16(uint32_t dst, const void* src) {
    asm volatile("cp.async.cg.shared.global [%0], [%1], 16;" :: "r"(dst), "l"(src));
}
__device__ __forceinline__ void cp_commit() { asm volatile("cp.async.commit_group;"); }
template <int N> __device__ __forceinline__ void cp_wait() {
    asm volatile("cp.async.wait_group %0;" :: "n"(N));
}
#define SW(o) ((o) ^ (((o) >> 3) & 0x70))

#if HAS_TCGEN05
__device__ __forceinline__ uint32_t elect1() {
    uint32_t p;
    asm volatile("{ .reg .pred p; elect.sync _|p, 0xFFFFFFFF; selp.b32 %0, 1, 0, p; }" : "=r"(p));
    return p;
}

#define MBARRIER_INIT(addr, cnt) \
    asm volatile("mbarrier.init.shared.b64 [%0], %1;" :: "r"((uint32_t)(addr)), "r"((uint32_t)(cnt)) : "memory")
#define MBARRIER_ARRIVE(addr) \
    asm volatile("mbarrier.arrive.shared.b64 _, [%0];" :: "r"((uint32_t)(addr)) : "memory")

#define MBAR_WAIT(addr, parity) do {                                              \
    uint32_t _mb = (uint32_t)(addr); uint32_t _pa = (uint32_t)(parity);           \
    asm volatile("{\n\t.reg .pred P1;\n\t"                                        \
        "WAIT_LOOP_%=:\n\t"                                                       \
        "mbarrier.try_wait.parity.acquire.cta.shared::cta.b64 P1, [%0], %1, 0x989680;\n\t" \
        "@P1 bra.uni WAIT_DONE_%=;\n\t"                                           \
        "bra.uni WAIT_LOOP_%=;\n\t"                                               \
        "WAIT_DONE_%=:\n\t}"                                                      \
        :: "r"(_mb), "r"(_pa) : "memory");                                        \
} while (0)

#define LDTM32(r, addr) \
    asm volatile("tcgen05.ld.sync.aligned.32x32b.x32.b32 " \
        "{%0, %1, %2, %3, %4, %5, %6, %7, %8, %9, %10, %11, %12, %13, %14, %15, " \
        "%16, %17, %18, %19, %20, %21, %22, %23, %24, %25, %26, %27, %28, %29, %30, %31}, [%32];" \
        : "=r"((r)[0]), "=r"((r)[1]), "=r"((r)[2]), "=r"((r)[3]),   \
          "=r"((r)[4]), "=r"((r)[5]), "=r"((r)[6]), "=r"((r)[7]),   \
          "=r"((r)[8]), "=r"((r)[9]), "=r"((r)[10]), "=r"((r)[11]), \
          "=r"((r)[12]), "=r"((r)[13]), "=r"((r)[14]), "=r"((r)[15]),\
          "=r"((r)[16]), "=r"((r)[17]), "=r"((r)[18]), "=r"((r)[19]),\
          "=r"((r)[20]), "=r"((r)[21]), "=r"((r)[22]), "=r"((r)[23]),\
          "=r"((r)[24]), "=r"((r)[25]), "=r"((r)[26]), "=r"((r)[27]),\
          "=r"((r)[28]), "=r"((r)[29]), "=r"((r)[30]), "=r"((r)[31]) \
        : "r"(addr))

__device__ __forceinline__ uint64_t DESC(uint32_t addr) {
    // SW128 K-major: layout=2, version=1, SBO=64 (1024B / 8 rows), LBO=1 (16B)
    return (2ULL << 61) | (1ULL << 46) | (64ULL << 32) | (1ULL << 16)
         | (uint64_t)((addr >> 4) & 0x3FFF);
}

// tf32 SS MMA, cta_group::1: D[128x256] += A[128xK8] @ B[256xK8]^T
__device__ __forceinline__ void mma_tf32_ss(uint32_t d, uint64_t ad, uint64_t bd,
                                            uint32_t idesc, uint32_t en) {
    asm volatile("{\n\t.reg .pred p;\n\tsetp.ne.u32 p, %4, 0;\n\t"
        "tcgen05.mma.cta_group::1.kind::tf32 [%0], %1, %2, %3, {%5, %5, %5, %5}, p;\n\t}"
        :: "r"(d), "l"(ad), "l"(bd), "r"(idesc), "r"(en), "r"(0u) : "memory");
}

#define TC_COMMIT(mb) \
    asm volatile("tcgen05.commit.cta_group::1.mbarrier::arrive::one.shared::cluster.b64 [%0];" \
                 :: "r"((uint32_t)(mb)) : "memory")

// idesc: dtype=F32(1)<<4, atype=TF32(2)<<7, btype=TF32(2)<<10, N/8<<17, M/16<<24
#define IDESC_TF32 ((1u << 4) | (2u << 7) | (2u << 10) | ((256u / 8) << 17) | ((128u / 16) << 24))
#endif  // HAS_TCGEN05

// ---------------- prep: transpose + tf32 rounding ----------------
__global__ void tr_kernel(const float* __restrict__ src, int R, int C, int which) {
    float* dst = which ? g_W2T : g_W1T;   // dst is [C][R]
    __shared__ float tile[32][33];
    int bx = blockIdx.x, by = blockIdx.y;
    int tx = threadIdx.x, ty = threadIdx.y;   // block (32, 8)
    #pragma unroll
    for (int i = 0; i < 4; i++)
        tile[ty + 8 * i][tx] = src[(size_t)(by * 32 + ty + 8 * i) * C + bx * 32 + tx];
    __syncthreads();
    #pragma unroll
    for (int i = 0; i < 4; i++)
        dst[(size_t)(bx * 32 + ty + 8 * i) * R + by * 32 + tx] = to_tf32(tile[tx][ty + 8 * i]);
}

// ---------------- K1: layers 0+1 fused -> h1 ----------------
// grid (1024, 2): 256 rows per CTA, 256-col N-half per CTA. K=1024, KC=32, T=32 chunks.
// Warp specialization: warps 0-3 = A producer (compute h0), warps 4-6 = B producer
// (cp.async W1T), warp 7 = MMA consumer. 3-stage ring, no __syncthreads in mainloop.
#define K1_SM_A  0                   // 3 x 32768  (A tiles 256x32 f32, SW128)
#define K1_SM_B  98304               // 3 x 32768  (B tiles 256x32 f32, SW128)
#define K1_SM_W0 196608              // 2048 f
#define K1_SM_B0 204800              // 1024 f
#define K1_SM_CO 208896              // 512 f
#define K1_SM_BI 210944              // 256 f
#define K1_SM_TP 211968
#define K1_SM_BAR 211976             // full_a[3], full_b[3], done[3], final = 10 x 8B
#define K1_SMEM  212096

#define BAR_FA(base, s) ((base) + (s) * 8)
#define BAR_FB(base, s) ((base) + 24 + (s) * 8)
#define BAR_DN(base, s) ((base) + 48 + (s) * 8)
#define BAR_FIN(base)   ((base) + 72)

__global__ void __launch_bounds__(THREADS, 1) k1_kernel(
    const float* __restrict__ coord, const float* __restrict__ W0,
    const float* __restrict__ b0, const float* __restrict__ W1,
    const float* __restrict__ b1)
{
#if HAS_TCGEN05
    extern __shared__ char sm[];
    const uint32_t smb = s2u(sm);
    const uint32_t barb = smb + K1_SM_BAR;
    const int tid  = threadIdx.x;
    const int wid  = tid >> 5;
    const int row0 = blockIdx.x * 256;
    const int n0   = blockIdx.y * 256;

    if (wid == 0)
        asm volatile("tcgen05.alloc.cta_group::1.sync.aligned.shared::cta.b32 [%0], %1;"
                     :: "r"(smb + K1_SM_TP), "r"(512) : "memory");
    if (tid == 0) {
        #pragma unroll
        for (int s = 0; s < 3; ++s) {
            MBARRIER_INIT(BAR_FA(barb, s), 128);
            MBARRIER_INIT(BAR_FB(barb, s), 96);
            MBARRIER_INIT(BAR_DN(barb, s), 1);
        }
        MBARRIER_INIT(BAR_FIN(barb), 1);
    }

    float* sW0 = (float*)(sm + K1_SM_W0);
    float* sB0 = (float*)(sm + K1_SM_B0);
    float* sCO = (float*)(sm + K1_SM_CO);
    float* sBI = (float*)(sm + K1_SM_BI);
    for (int i = tid; i < 2048; i += 256) sW0[i] = W0[i];
    for (int i = tid; i < 1024; i += 256) sB0[i] = b0[i];
    ((float2*)sCO)[tid] = ((const float2*)coord)[row0 + tid];
    sBI[tid] = b1[n0 + tid];
    __syncthreads();

    uint32_t tmem;
    asm volatile("ld.shared.b32 %0, [%1];" : "=r"(tmem) : "r"(smb + K1_SM_TP));

    if (wid < 4) {
        // ---- A producer: compute h0 chunk (layer 0), 2 rows/thread ----
        const int r0a = tid;            // rows tid and tid+128
        const int r1a = tid + 128;
        const float c0a = sCO[2 * r0a], c1a = sCO[2 * r0a + 1];
        const float c0b = sCO[2 * r1a], c1b = sCO[2 * r1a + 1];
        for (int t = 0; t < 32; ++t) {
            const int s = t % 3, u = t / 3;
            MBAR_WAIT(BAR_DN(barb, s), (u + 1) & 1);   // stage free (passes for u=0)
            char* ab = sm + K1_SM_A + s * 32768;
            #pragma unroll
            for (int q = 0; q < 8; ++q) {
                int k = t * 32 + q * 4;
                float4 wa = *(const float4*)&sW0[k];
                float4 wb = *(const float4*)&sW0[1024 + k];
                float4 bb = *(const float4*)&sB0[k];
                float4 v;
                v.x = to_tf32(fmaxf(fmaf(c0a, wa.x, fmaf(c1a, wb.x, bb.x)), 0.f));
                v.y = to_tf32(fmaxf(fmaf(c0a, wa.y, fmaf(c1a, wb.y, bb.y)), 0.f));
                v.z = to_tf32(fmaxf(fmaf(c0a, wa.z, fmaf(c1a, wb.z, bb.z)), 0.f));
                v.w = to_tf32(fmaxf(fmaf(c0a, wa.w, fmaf(c1a, wb.w, bb.w)), 0.f));
                *(float4*)(ab + SW(r0a * 128 + q * 16)) = v;
                v.x = to_tf32(fmaxf(fmaf(c0b, wa.x, fmaf(c1b, wb.x, bb.x)), 0.f));
                v.y = to_tf32(fmaxf(fmaf(c0b, wa.y, fmaf(c1b, wb.y, bb.y)), 0.f));
                v.z = to_tf32(fmaxf(fmaf(c0b, wa.z, fmaf(c1b, wb.z, bb.z)), 0.f));
                v.w = to_tf32(fmaxf(fmaf(c0b, wa.w, fmaf(c1b, wb.w, bb.w)), 0.f));
                *(float4*)(ab + SW(r1a * 128 + q * 16)) = v;
            }
            asm volatile("fence.proxy.async.shared::cta;" ::: "memory");
            MBARRIER_ARRIVE(BAR_FA(barb, s));
        }
    } else if (wid < 7) {
        // ---- B producer: cp.async W1T chunk rows [n0, n0+256) ----
        const int ptid = tid - 128;     // 0..95
        for (int t = 0; t < 32; ++t) {
            const int s = t % 3, u = t / 3;
            MBAR_WAIT(BAR_DN(barb, s), (u + 1) & 1);
            uint32_t db = smb + K1_SM_B + s * 32768;
            for (int e = ptid; e < 2048; e += 96) {
                int r = e >> 3, seg = e & 7;
                cp16(db + SW(r * 128 + seg * 16),
                     g_W1T + (size_t)(n0 + r) * 1024 + t * 32 + seg * 4);
            }
            cp_commit();
            cp_wait<0>();
            asm volatile("fence.proxy.async.shared::cta;" ::: "memory");
            MBARRIER_ARRIVE(BAR_FB(barb, s));
        }
    } else {
        // ---- MMA consumer (warp 7) ----
        for (int t = 0; t < 32; ++t) {
            const int s = t % 3, u = t / 3;
            MBAR_WAIT(BAR_FA(barb, s), u & 1);
            MBAR_WAIT(BAR_FB(barb, s), u & 1);
            if (elect1()) {
                uint64_t ad = DESC(smb + K1_SM_A + s * 32768);
                uint64_t bd = DESC(smb + K1_SM_B + s * 32768);
                #pragma unroll
                for (int st = 0; st < 4; ++st) {
                    uint32_t en = (t > 0 || st > 0) ? 1u : 0u;
                    mma_tf32_ss(tmem,       ad + 2 * st,        bd + 2 * st, IDESC_TF32, en);
                    mma_tf32_ss(tmem + 256, ad + 1024 + 2 * st, bd + 2 * st, IDESC_TF32, en);
                }
                TC_COMMIT(BAR_DN(barb, s));
            }
        }
        if (elect1()) TC_COMMIT(BAR_FIN(barb));   // tracks ALL prior MMAs
    }

    // ---- all threads: wait for every MMA, then epilogue ----
    MBAR_WAIT(BAR_FIN(barb), 0);
    asm volatile("tcgen05.fence::after_thread_sync;" ::: "memory");

    // epilogue: bias + relu + tf32 round -> h1
    const int w = tid >> 5, lane = tid & 31;
    const int sub = w >> 2;
    const int grow = row0 + sub * 128 + ((w & 3) << 5) + lane;
    float* h1row = g_h1 + (size_t)grow * 512 + n0;
    #pragma unroll
    for (int cc = 0; cc < 8; ++cc) {
        uint32_t r[32];
        LDTM32(r, tmem + sub * 256 + cc * 32);
        asm volatile("tcgen05.wait::ld.sync.aligned;" ::: "memory");
        #pragma unroll
        for (int q = 0; q < 8; ++q) {
            float4 bb = *(const float4*)&sBI[cc * 32 + q * 4];
            float4 v;
            v.x = to_tf32(fmaxf(__uint_as_float(r[q * 4 + 0]) + bb.x, 0.f));
            v.y = to_tf32(fmaxf(__uint_as_float(r[q * 4 + 1]) + bb.y, 0.f));
            v.z = to_tf32(fmaxf(__uint_as_float(r[q * 4 + 2]) + bb.z, 0.f));
            v.w = to_tf32(fmaxf(__uint_as_float(r[q * 4 + 3]) + bb.w, 0.f));
            *(float4*)&h1row[cc * 32 + q * 4] = v;
        }
    }
    __syncthreads();
    if (tid < 32) {
        asm volatile("tcgen05.relinquish_alloc_permit.cta_group::1.sync.aligned;");
        asm volatile("tcgen05.dealloc.cta_group::1.sync.aligned.b32 %0, %1;" :: "r"(tmem), "r"(512));
    }
#else
    // -------- fallback (non-103a compile pass): plain-FMA, same semantics --------
    extern __shared__ char sm[];
    float* h0g = (float*)sm;                       // 8 x 1024 floats
    const int tid  = threadIdx.x;
    const int row0 = blockIdx.x * 256;
    const int n0   = blockIdx.y * 256;
    const int rg   = tid >> 5, lane = tid & 31;
    const int cbase = n0 + lane * 8;

    for (int g = 0; g < 32; ++g) {                 // 8-row groups
        int rbase = row0 + g * 8;
        for (int i = tid; i < 8192; i += 256) {
            int r = i >> 10, k = i & 1023;
            float c0 = coord[(rbase + r) * 2], c1 = coord[(rbase + r) * 2 + 1];
            h0g[i] = fmaxf(fmaf(c0, W0[k], fmaf(c1, W0[1024 + k], b0[k])), 0.f);
        }
        __syncthreads();
        float acc[8];
        #pragma unroll
        for (int j = 0; j < 8; j++) acc[j] = b1[cbase + j];
        for (int k = 0; k < 1024; ++k) {
            float a = h0g[rg * 1024 + k];
            float4 w0_ = *(const float4*)&W1[(size_t)k * 512 + cbase];
            float4 w1_ = *(const float4*)&W1[(size_t)k * 512 + cbase + 4];
            acc[0] = fmaf(a, w0_.x, acc[0]); acc[1] = fmaf(a, w0_.y, acc[1]);
            acc[2] = fmaf(a, w0_.z, acc[2]); acc[3] = fmaf(a, w0_.w, acc[3]);
            acc[4] = fmaf(a, w1_.x, acc[4]); acc[5] = fmaf(a, w1_.y, acc[5]);
            acc[6] = fmaf(a, w1_.z, acc[6]); acc[7] = fmaf(a, w1_.w, acc[7]);
        }
        float* dst = g_h1 + (size_t)(rbase + rg) * 512 + cbase;
        #pragma unroll
        for (int j = 0; j < 8; j++) dst[j] = fmaxf(acc[j], 0.f);
        __syncthreads();
    }
#endif
}

// ---------------- K2: layers 2+3 fused -> out ----------------
// grid (1024): 256 rows per CTA, N=256 (full). K=512, KC=32, T=16 chunks.
#define K2_SM_A   0                  // 3 x 32768
#define K2_SM_B   98304              // 3 x 32768
#define K2_SM_B2  196608             // 256 f
#define K2_SM_W3  197632             // 1024 f (padded 4/col)
#define K2_SM_B3  201728             // 4 f
#define K2_SM_TP  201744
#define K2_SM_BAR 201752             // 10 x 8B
#define K2_SMEM   201856

__global__ void __launch_bounds__(THREADS, 1) k2_kernel(
    const float* __restrict__ W2, const float* __restrict__ b2,
    const float* __restrict__ W3, const float* __restrict__ b3,
    float* __restrict__ out)
{
#if HAS_TCGEN05
    extern __shared__ char sm[];
    const uint32_t smb = s2u(sm);
    const uint32_t barb = smb + K2_SM_BAR;
    const int tid  = threadIdx.x;
    const int wid  = tid >> 5;
    const int row0 = blockIdx.x * 256;

    if (wid == 0)
        asm volatile("tcgen05.alloc.cta_group::1.sync.aligned.shared::cta.b32 [%0], %1;"
                     :: "r"(smb + K2_SM_TP), "r"(512) : "memory");
    if (tid == 0) {
        #pragma unroll
        for (int s = 0; s < 3; ++s) {
            MBARRIER_INIT(BAR_FA(barb, s), 128);
            MBARRIER_INIT(BAR_FB(barb, s), 96);
            MBARRIER_INIT(BAR_DN(barb, s), 1);
        }
        MBARRIER_INIT(BAR_FIN(barb), 1);
    }

    float* sB2 = (float*)(sm + K2_SM_B2);
    float* sW3 = (float*)(sm + K2_SM_W3);
    float* sB3 = (float*)(sm + K2_SM_B3);
    sB2[tid] = b2[tid];
    for (int i = tid; i < 768; i += 256) sW3[(i / 3) * 4 + (i % 3)] = W3[i];
    if (tid < 3) sB3[tid] = b3[tid];
    __syncthreads();

    uint32_t tmem;
    asm volatile("ld.shared.b32 %0, [%1];" : "=r"(tmem) : "r"(smb + K2_SM_TP));

    if (wid < 4) {
        // ---- A producer: cp.async h1 rows [row0, row0+256) ----
        for (int t = 0; t < 16; ++t) {
            const int s = t % 3, u = t / 3;
            MBAR_WAIT(BAR_DN(barb, s), (u + 1) & 1);
            uint32_t da = smb + K2_SM_A + s * 32768;
            #pragma unroll
            for (int i = 0; i < 16; ++i) {
                int e = tid + 128 * i;
                int r = e >> 3, seg = e & 7;
                cp16(da + SW(r * 128 + seg * 16),
                     g_h1 + (size_t)(row0 + r) * 512 + t * 32 + seg * 4);
            }
            cp_commit();
            cp_wait<0>();
            asm volatile("fence.proxy.async.shared::cta;" ::: "memory");
            MBARRIER_ARRIVE(BAR_FA(barb, s));
        }
    } else if (wid < 7) {
        // ---- B producer: cp.async W2T rows [0, 256) ----
        const int ptid = tid - 128;
        for (int t = 0; t < 16; ++t) {
            const int s = t % 3, u = t / 3;
            MBAR_WAIT(BAR_DN(barb, s), (u + 1) & 1);
            uint32_t db = smb + K2_SM_B + s * 32768;
            for (int e = ptid; e < 2048; e += 96) {
                int r = e >> 3, seg = e & 7;
                cp16(db + SW(r * 128 + seg * 16),
                     g_W2T + (size_t)r * 512 + t * 32 + seg * 4);
            }
            cp_commit();
            cp_wait<0>();
            asm volatile("fence.proxy.async.shared::cta;" ::: "memory");
            MBARRIER_ARRIVE(BAR_FB(barb, s));
        }
    } else {
        // ---- MMA consumer ----
        for (int t = 0; t < 16; ++t) {
            const int s = t % 3, u = t / 3;
            MBAR_WAIT(BAR_FA(barb, s), u & 1);
            MBAR_WAIT(BAR_FB(barb, s), u & 1);
            if (elect1()) {
                uint64_t ad = DESC(smb + K2_SM_A + s * 32768);
                uint64_t bd = DESC(smb + K2_SM_B + s * 32768);
                #pragma unroll
                for (int st = 0; st < 4; ++st) {
                    uint32_t en = (t > 0 || st > 0) ? 1u : 0u;
                    mma_tf32_ss(tmem,       ad + 2 * st,        bd + 2 * st, IDESC_TF32, en);
                    mma_tf32_ss(tmem + 256, ad + 1024 + 2 * st, bd + 2 * st, IDESC_TF32, en);
                }
                TC_COMMIT(BAR_DN(barb, s));
            }
        }
        if (elect1()) TC_COMMIT(BAR_FIN(barb));
    }

    MBAR_WAIT(BAR_FIN(barb), 0);
    asm volatile("tcgen05.fence::after_thread_sync;" ::: "memory");

    // epilogue: h2 = relu(D + b2); out = h2 @ W3 + b3 (h2 never hits global)
    const int w = tid >> 5, lane = tid & 31;
    const int sub = w >> 2;
    const int grow = row0 + sub * 128 + ((w & 3) << 5) + lane;
    float a0 = 0.f, a1 = 0.f, a2 = 0.f;
    #pragma unroll
    for (int cc = 0; cc < 8; ++cc) {
        uint32_t r[32];
        LDTM32(r, tmem + sub * 256 + cc * 32);
        asm volatile("tcgen05.wait::ld.sync.aligned;" ::: "memory");
        #pragma unroll
        for (int q = 0; q < 8; ++q) {
            float4 bb = *(const float4*)&sB2[cc * 32 + q * 4];
            #pragma unroll
            for (int m = 0; m < 4; ++m) {
                float bbm = (m == 0) ? bb.x : (m == 1) ? bb.y : (m == 2) ? bb.z : bb.w;
                float h = fmaxf(__uint_as_float(r[q * 4 + m]) + bbm, 0.f);
                float4 w3 = *(const float4*)&sW3[(cc * 32 + q * 4 + m) * 4];
                a0 = fmaf(h, w3.x, a0);
                a1 = fmaf(h, w3.y, a1);
                a2 = fmaf(h, w3.z, a2);
            }
        }
    }
    out[(size_t)grow * 3 + 0] = a0 + sB3[0];
    out[(size_t)grow * 3 + 1] = a1 + sB3[1];
    out[(size_t)grow * 3 + 2] = a2 + sB3[2];

    __syncthreads();
    if (tid < 32) {
        asm volatile("tcgen05.relinquish_alloc_permit.cta_group::1.sync.aligned;");
        asm volatile("tcgen05.dealloc.cta_group::1.sync.aligned.b32 %0, %1;" :: "r"(tmem), "r"(512));
    }
#else
    // -------- fallback (non-103a compile pass): plain-FMA, same semantics --------
    extern __shared__ char sm[];
    float* h1g = (float*)sm;                       // 8 x 512
    float* h2g = h1g + 4096;                       // 8 x 256
    const int tid  = threadIdx.x;
    const int row0 = blockIdx.x * 256;
    const int rg   = tid >> 5, lane = tid & 31;
    const int cbase = lane * 8;

    for (int g = 0; g < 32; ++g) {
        int rbase = row0 + g * 8;
        for (int i = tid; i < 4096; i += 256)
            h1g[i] = g_h1[(size_t)(rbase + (i >> 9)) * 512 + (i & 511)];
        __syncthreads();
        float acc[8];
        #pragma unroll
        for (int j = 0; j < 8; j++) acc[j] = b2[cbase + j];
        for (int k = 0; k < 512; ++k) {
            float a = h1g[rg * 512 + k];
            float4 w0_ = *(const float4*)&W2[(size_t)k * 256 + cbase];
            float4 w1_ = *(const float4*)&W2[(size_t)k * 256 + cbase + 4];
            acc[0] = fmaf(a, w0_.x, acc[0]); acc[1] = fmaf(a, w0_.y, acc[1]);
            acc[2] = fmaf(a, w0_.z, acc[2]); acc[3] = fmaf(a, w0_.w, acc[3]);
            acc[4] = fmaf(a, w1_.x, acc[4]); acc[5] = fmaf(a, w1_.y, acc[5]);
            acc[6] = fmaf(a, w1_.z, acc[6]); acc[7] = fmaf(a, w1_.w, acc[7]);
        }
        #pragma unroll
        for (int j = 0; j < 8; j++) h2g[rg * 256 + cbase + j] = fmaxf(acc[j], 0.f);
        __syncthreads();
        if (tid < 24) {
            int m = tid / 3, c = tid - m * 3;
            float s = b3[c];
            for (int k = 0; k < 256; ++k) s = fmaf(h2g[m * 256 + k], W3[k * 3 + c], s);
            out[(size_t)(rbase + m) * 3 + c] = s;
        }
        __syncthreads();
    }
#endif
}

// ---------------- launch ----------------
extern "C" void kernel_launch(void* const* d_in, const int* in_sizes, int n_in,
                              void* d_out, int out_size) {
    const float* coord = (const float*)d_in[0];
    const float* W0 = (const float*)d_in[1];
    const float* b0 = (const float*)d_in[2];
    const float* W1 = (const float*)d_in[3];
    const float* b1 = (const float*)d_in[4];
    const float* W2 = (const float*)d_in[5];
    const float* b2 = (const float*)d_in[6];
    const float* W3 = (const float*)d_in[7];
    const float* b3 = (const float*)d_in[8];
    float* out = (float*)d_out;

    cudaFuncSetAttribute(k1_kernel, cudaFuncAttributeMaxDynamicSharedMemorySize, K1_SMEM);
    cudaFuncSetAttribute(k2_kernel, cudaFuncAttributeMaxDynamicSharedMemorySize, K2_SMEM);

    // prep: W1 [1024x512] -> W1T [512x1024]; W2 [512x256] -> W2T [256x512]
    tr_kernel<<<dim3(512 / 32, 1024 / 32), dim3(32, 8)>>>(W1, 1024, 512, 0);
    tr_kernel<<<dim3(256 / 32,  512 / 32), dim3(32, 8)>>>(W2,  512, 256, 1);

    // layers 0+1 -> h1
    k1_kernel<<<dim3(1024, 2), THREADS, K1_SMEM>>>(coord, W0, b0, W1, b1);
    // layers 2+3 -> out
    k2_kernel<<<dim3(1024, 1), THREADS, K2_SMEM>>>(W2, b2, W3, b3, out);
}